// round 1
// baseline (speedup 1.0000x reference)
#include <cuda_runtime.h>
#include <math.h>

#define BB 8
#define SS 2048
#define DD 768

// Scratch (device globals: allocation-free per harness rules)
__device__ float g_Q[BB * SS * DD];
__device__ float g_K[BB * SS * DD];
__device__ float g_V[BB * SS * DD];
__device__ float g_O[BB * SS * DD];
__device__ float g_P[(size_t)BB * SS * SS];   // 134 MB attention matrix

// ---------------------------------------------------------------------------
// C[M,N] = alpha * A[M,K] @ B[N,K]^T + bias   (both operands K-contiguous)
// 128x128 block tile, BK=16, 256 threads, 8x8 per-thread (split 4+4).
// All dims here are multiples of the tile sizes -> no predication.
// ---------------------------------------------------------------------------
__global__ __launch_bounds__(256) void gemm_nt_kernel(
    const float* __restrict__ A, const float* __restrict__ Bm,
    const float* __restrict__ bias, float* __restrict__ C,
    int M, int N, int K, float alpha,
    size_t sA, size_t sB, size_t sC)
{
    constexpr int BM = 128, BN = 128, BK = 16;
    __shared__ float As[BK][BM];
    __shared__ float Bs[BK][BN];

    const float* Ab = A + blockIdx.z * sA;
    const float* Bb = Bm + blockIdx.z * sB;
    float* Cb = C + blockIdx.z * sC;

    const int bm = blockIdx.y * BM;
    const int bn = blockIdx.x * BN;
    const int tid = threadIdx.x;
    const int tx = tid & 15;
    const int ty = tid >> 4;

    float acc[8][8];
    #pragma unroll
    for (int i = 0; i < 8; i++)
        #pragma unroll
        for (int j = 0; j < 8; j++) acc[i][j] = 0.0f;

    const int lrow = tid >> 2;        // 0..63 (second half at +64)
    const int lk   = (tid & 3) << 2;  // 0,4,8,12

    for (int k0 = 0; k0 < K; k0 += BK) {
        #pragma unroll
        for (int h = 0; h < 2; h++) {
            const int row = lrow + h * 64;
            float4 va = *(const float4*)(Ab + (size_t)(bm + row) * K + (k0 + lk));
            As[lk + 0][row] = va.x; As[lk + 1][row] = va.y;
            As[lk + 2][row] = va.z; As[lk + 3][row] = va.w;
            float4 vb = *(const float4*)(Bb + (size_t)(bn + row) * K + (k0 + lk));
            Bs[lk + 0][row] = vb.x; Bs[lk + 1][row] = vb.y;
            Bs[lk + 2][row] = vb.z; Bs[lk + 3][row] = vb.w;
        }
        __syncthreads();

        #pragma unroll
        for (int k = 0; k < BK; k++) {
            float a[8], b[8];
            *(float4*)(a)     = *(const float4*)&As[k][ty * 4];
            *(float4*)(a + 4) = *(const float4*)&As[k][ty * 4 + 64];
            *(float4*)(b)     = *(const float4*)&Bs[k][tx * 4];
            *(float4*)(b + 4) = *(const float4*)&Bs[k][tx * 4 + 64];
            #pragma unroll
            for (int i = 0; i < 8; i++)
                #pragma unroll
                for (int j = 0; j < 8; j++)
                    acc[i][j] = fmaf(a[i], b[j], acc[i][j]);
        }
        __syncthreads();
    }

    float bvv[8];
    if (bias) {
        *(float4*)(bvv)     = *(const float4*)(bias + bn + tx * 4);
        *(float4*)(bvv + 4) = *(const float4*)(bias + bn + tx * 4 + 64);
    } else {
        #pragma unroll
        for (int j = 0; j < 8; j++) bvv[j] = 0.0f;
    }

    #pragma unroll
    for (int i = 0; i < 8; i++) {
        const int row = bm + ((i < 4) ? (ty * 4 + i) : (64 + ty * 4 + i - 4));
        float4 o0, o1;
        o0.x = alpha * acc[i][0] + bvv[0];
        o0.y = alpha * acc[i][1] + bvv[1];
        o0.z = alpha * acc[i][2] + bvv[2];
        o0.w = alpha * acc[i][3] + bvv[3];
        o1.x = alpha * acc[i][4] + bvv[4];
        o1.y = alpha * acc[i][5] + bvv[5];
        o1.z = alpha * acc[i][6] + bvv[6];
        o1.w = alpha * acc[i][7] + bvv[7];
        *(float4*)(Cb + (size_t)row * N + bn + tx * 4)      = o0;
        *(float4*)(Cb + (size_t)row * N + bn + tx * 4 + 64) = o1;
    }
}

// ---------------------------------------------------------------------------
// C[M,N] = A[M,K] @ B[K,N]   (B is N-contiguous) — used for P @ V
// ---------------------------------------------------------------------------
__global__ __launch_bounds__(256) void gemm_nn_kernel(
    const float* __restrict__ A, const float* __restrict__ Bm,
    float* __restrict__ C,
    int M, int N, int K,
    size_t sA, size_t sB, size_t sC)
{
    constexpr int BM = 128, BN = 128, BK = 16;
    __shared__ float As[BK][BM];
    __shared__ float Bs[BK][BN];

    const float* Ab = A + blockIdx.z * sA;
    const float* Bb = Bm + blockIdx.z * sB;
    float* Cb = C + blockIdx.z * sC;

    const int bm = blockIdx.y * BM;
    const int bn = blockIdx.x * BN;
    const int tid = threadIdx.x;
    const int tx = tid & 15;
    const int ty = tid >> 4;

    float acc[8][8];
    #pragma unroll
    for (int i = 0; i < 8; i++)
        #pragma unroll
        for (int j = 0; j < 8; j++) acc[i][j] = 0.0f;

    const int larow = tid >> 2;
    const int lak   = (tid & 3) << 2;
    const int lbk   = tid >> 5;        // 0..7 (second half +8)
    const int lbn   = (tid & 31) << 2; // 0..124

    for (int k0 = 0; k0 < K; k0 += BK) {
        #pragma unroll
        for (int h = 0; h < 2; h++) {
            const int row = larow + h * 64;
            float4 va = *(const float4*)(Ab + (size_t)(bm + row) * K + (k0 + lak));
            As[lak + 0][row] = va.x; As[lak + 1][row] = va.y;
            As[lak + 2][row] = va.z; As[lak + 3][row] = va.w;
            const int kr = lbk + h * 8;
            float4 vb = *(const float4*)(Bb + (size_t)(k0 + kr) * N + bn + lbn);
            *(float4*)&Bs[kr][lbn] = vb;
        }
        __syncthreads();

        #pragma unroll
        for (int k = 0; k < BK; k++) {
            float a[8], b[8];
            *(float4*)(a)     = *(const float4*)&As[k][ty * 4];
            *(float4*)(a + 4) = *(const float4*)&As[k][ty * 4 + 64];
            *(float4*)(b)     = *(const float4*)&Bs[k][tx * 4];
            *(float4*)(b + 4) = *(const float4*)&Bs[k][tx * 4 + 64];
            #pragma unroll
            for (int i = 0; i < 8; i++)
                #pragma unroll
                for (int j = 0; j < 8; j++)
                    acc[i][j] = fmaf(a[i], b[j], acc[i][j]);
        }
        __syncthreads();
    }

    #pragma unroll
    for (int i = 0; i < 8; i++) {
        const int row = bm + ((i < 4) ? (ty * 4 + i) : (64 + ty * 4 + i - 4));
        float4 o0, o1;
        o0.x = acc[i][0]; o0.y = acc[i][1]; o0.z = acc[i][2]; o0.w = acc[i][3];
        o1.x = acc[i][4]; o1.y = acc[i][5]; o1.z = acc[i][6]; o1.w = acc[i][7];
        *(float4*)(Cb + (size_t)row * N + bn + tx * 4)      = o0;
        *(float4*)(Cb + (size_t)row * N + bn + tx * 4 + 64) = o1;
    }
}

// ---------------------------------------------------------------------------
// Row softmax over S=2048. One block per row; all values register-resident:
// one global read + one global write per element.
// ---------------------------------------------------------------------------
__global__ __launch_bounds__(256) void softmax_kernel(float* __restrict__ P)
{
    float* row = P + (size_t)blockIdx.x * SS;
    const int tid = threadIdx.x;
    __shared__ float red[8];

    float4 v0 = ((const float4*)row)[tid];
    float4 v1 = ((const float4*)row)[tid + 256];

    float m = fmaxf(fmaxf(fmaxf(v0.x, v0.y), fmaxf(v0.z, v0.w)),
                    fmaxf(fmaxf(v1.x, v1.y), fmaxf(v1.z, v1.w)));
    #pragma unroll
    for (int o = 16; o > 0; o >>= 1)
        m = fmaxf(m, __shfl_xor_sync(0xffffffffu, m, o));
    if ((tid & 31) == 0) red[tid >> 5] = m;
    __syncthreads();
    float bmax = red[0];
    #pragma unroll
    for (int i = 1; i < 8; i++) bmax = fmaxf(bmax, red[i]);
    __syncthreads();

    v0.x = __expf(v0.x - bmax); v0.y = __expf(v0.y - bmax);
    v0.z = __expf(v0.z - bmax); v0.w = __expf(v0.w - bmax);
    v1.x = __expf(v1.x - bmax); v1.y = __expf(v1.y - bmax);
    v1.z = __expf(v1.z - bmax); v1.w = __expf(v1.w - bmax);

    float s = v0.x + v0.y + v0.z + v0.w + v1.x + v1.y + v1.z + v1.w;
    #pragma unroll
    for (int o = 16; o > 0; o >>= 1)
        s += __shfl_xor_sync(0xffffffffu, s, o);
    if ((tid & 31) == 0) red[tid >> 5] = s;
    __syncthreads();
    float total = 0.0f;
    #pragma unroll
    for (int i = 0; i < 8; i++) total += red[i];

    const float inv = __frcp_rn(total);
    v0.x *= inv; v0.y *= inv; v0.z *= inv; v0.w *= inv;
    v1.x *= inv; v1.y *= inv; v1.z *= inv; v1.w *= inv;
    ((float4*)row)[tid]       = v0;
    ((float4*)row)[tid + 256] = v1;
}

// ---------------------------------------------------------------------------
extern "C" void kernel_launch(void* const* d_in, const int* in_sizes, int n_in,
                              void* d_out, int out_size)
{
    const float* x  = (const float*)d_in[0];
    const float* Wq = (const float*)d_in[1];
    const float* bq = (const float*)d_in[2];
    const float* Wk = (const float*)d_in[3];
    const float* bk = (const float*)d_in[4];
    const float* Wv = (const float*)d_in[5];
    const float* bv = (const float*)d_in[6];
    const float* Wp = (const float*)d_in[7];
    const float* bp = (const float*)d_in[8];
    float* out = (float*)d_out;

    float *Q, *K, *V, *O, *P;
    cudaGetSymbolAddress((void**)&Q, g_Q);
    cudaGetSymbolAddress((void**)&K, g_K);
    cudaGetSymbolAddress((void**)&V, g_V);
    cudaGetSymbolAddress((void**)&O, g_O);
    cudaGetSymbolAddress((void**)&P, g_P);

    const dim3 blk(256);
    const size_t sQK = (size_t)SS * DD;
    const size_t sP  = (size_t)SS * SS;
    const float alpha = 1.0f / sqrtf((float)DD);

    // QKV projections: [16384,768] = x @ W^T + b
    dim3 gproj(DD / 128, (BB * SS) / 128, 1);
    gemm_nt_kernel<<<gproj, blk>>>(x, Wq, bq, Q, BB * SS, DD, DD, 1.0f, 0, 0, 0);
    gemm_nt_kernel<<<gproj, blk>>>(x, Wk, bk, K, BB * SS, DD, DD, 1.0f, 0, 0, 0);
    gemm_nt_kernel<<<gproj, blk>>>(x, Wv, bv, V, BB * SS, DD, DD, 1.0f, 0, 0, 0);

    // P = (Q @ K^T) / sqrt(D), batched over B
    dim3 gs(SS / 128, SS / 128, BB);
    gemm_nt_kernel<<<gs, blk>>>(Q, K, nullptr, P, SS, SS, DD, alpha, sQK, sQK, sP);

    // softmax rows
    softmax_kernel<<<BB * SS, 256>>>(P);

    // O = P @ V, batched
    dim3 go(DD / 128, SS / 128, BB);
    gemm_nn_kernel<<<go, blk>>>(P, V, O, SS, DD, SS, sP, sQK, sQK);

    // out = O @ Wp^T + bp
    gemm_nt_kernel<<<gproj, blk>>>(O, Wp, bp, out, BB * SS, DD, DD, 1.0f, 0, 0, 0);
}

// round 7
// speedup vs baseline: 1.8317x; 1.8317x over previous
#include <cuda_runtime.h>
#include <cuda_bf16.h>
#include <math.h>
#include <stdint.h>

#define BB 8
#define SS 2048
#define DD 768

// ---------------------------------------------------------------------------
// Scratch (device globals: allocation-free per harness rules)
// ---------------------------------------------------------------------------
__device__ __nv_bfloat16 g_xhi[BB * SS * DD], g_xlo[BB * SS * DD];
__device__ __nv_bfloat16 g_Wqhi[DD * DD], g_Wqlo[DD * DD];
__device__ __nv_bfloat16 g_Wkhi[DD * DD], g_Wklo[DD * DD];
__device__ __nv_bfloat16 g_Wvhi[DD * DD], g_Wvlo[DD * DD];
__device__ __nv_bfloat16 g_Wphi[DD * DD], g_Wplo[DD * DD];
__device__ __nv_bfloat16 g_Qhi[BB * SS * DD], g_Qlo[BB * SS * DD];
__device__ __nv_bfloat16 g_Khi[BB * SS * DD], g_Klo[BB * SS * DD];
__device__ float         g_V[BB * SS * DD];
__device__ __nv_bfloat16 g_Vthi[BB * DD * SS], g_Vtlo[BB * DD * SS];
__device__ float         g_P[(size_t)BB * SS * SS];
__device__ __nv_bfloat16 g_Phi[(size_t)BB * SS * SS], g_Plo[(size_t)BB * SS * SS];
__device__ __nv_bfloat16 g_Ohi[BB * SS * DD], g_Olo[BB * SS * DD];

// ---------------------------------------------------------------------------
// Portable PTX helpers (no 'a'-gated features: ldmatrix / mma.sync / cp.async)
// ---------------------------------------------------------------------------
__device__ __forceinline__ uint32_t smem_to_u32(const void* p) {
    uint32_t a;
    asm("{ .reg .u64 t; cvta.to.shared.u64 t, %1; cvt.u32.u64 %0, t; }"
        : "=r"(a) : "l"(p));
    return a;
}

#define CP_ASYNC16(saddr, gaddr) \
    asm volatile("cp.async.cg.shared.global [%0], [%1], 16;" :: "r"(saddr), "l"(gaddr))
#define CP_COMMIT() asm volatile("cp.async.commit_group;" ::: "memory")
#define CP_WAIT(N)  asm volatile("cp.async.wait_group %0;" :: "n"(N) : "memory")

__device__ __forceinline__ void ldm_x4(uint32_t* r, uint32_t addr) {
    asm volatile("ldmatrix.sync.aligned.m8n8.x4.shared.b16 {%0,%1,%2,%3}, [%4];"
                 : "=r"(r[0]), "=r"(r[1]), "=r"(r[2]), "=r"(r[3]) : "r"(addr));
}

__device__ __forceinline__ void mma_bf16(float* c, const uint32_t* a,
                                         uint32_t b0, uint32_t b1) {
    asm volatile(
        "mma.sync.aligned.m16n8k16.row.col.f32.bf16.bf16.f32 "
        "{%0,%1,%2,%3}, {%4,%5,%6,%7}, {%8,%9}, {%0,%1,%2,%3};"
        : "+f"(c[0]), "+f"(c[1]), "+f"(c[2]), "+f"(c[3])
        : "r"(a[0]), "r"(a[1]), "r"(a[2]), "r"(a[3]), "r"(b0), "r"(b1));
}

__device__ __forceinline__ uint32_t pack_bf2(float a, float b) {
    __nv_bfloat162 t(__float2bfloat16(a), __float2bfloat16(b));
    return *reinterpret_cast<uint32_t*>(&t);
}

// ---------------------------------------------------------------------------
// Split-bf16 HMMA GEMM (NT): C[M,N] = alpha*(A @ B^T) + bias
//   A[M,K], B[N,K], both K-contiguous. hi/lo pairs; acc = hh + hl + lh (fp32).
//   128x128 block tile, BK=32, 256 threads, warp tile 32x64.
//   grid = (N/128, M/128, batch).
// ---------------------------------------------------------------------------
#define ROWB 80                      // smem row pitch bytes (64B data + 16B pad)
#define MATB (128 * ROWB)            // 10240 B per matrix tile
#define STGB (4 * MATB)              // 40960 B per stage (Ah,Al,Bh,Bl)
#define GEMM_SMEM_BYTES (2 * STGB)   // 81920

__global__ __launch_bounds__(256, 1) void mma_gemm(
    const __nv_bfloat16* __restrict__ Ahi, const __nv_bfloat16* __restrict__ Alo,
    const __nv_bfloat16* __restrict__ Bhi, const __nv_bfloat16* __restrict__ Blo,
    const float* __restrict__ bias, float alpha,
    float* __restrict__ Cf,
    __nv_bfloat16* __restrict__ Chi, __nv_bfloat16* __restrict__ Clo,
    int ldc, int K, size_t strA, size_t strB, size_t strC)
{
    extern __shared__ char smem[];
    const uint32_t sb = smem_to_u32(smem);

    const int tid = threadIdx.x;
    const int wid = tid >> 5;
    const int lid = tid & 31;
    const int bm = blockIdx.y << 7;
    const int bn = blockIdx.x << 7;
    const int wm = (wid & 3) << 5;   // warp row offset (0..96)
    const int wn = (wid >> 2) << 6;  // warp col offset (0,64)

    Ahi += blockIdx.z * strA; Alo += blockIdx.z * strA;
    Bhi += blockIdx.z * strB; Blo += blockIdx.z * strB;

    // ---- global->smem copy geometry (per matrix: 128 rows x 64B) ----
    const int grow = tid >> 1;               // 0..127
    const int ghalf = (tid & 1) << 4;        // element offset 0 / 16
    const uint32_t soff = grow * ROWB + ((tid & 1) << 5);  // byte off in tile

    auto issue_stage = [&](int c, int stg) {
        const int k0 = c << 5;
        const uint32_t s0 = sb + stg * STGB + soff;
        const __nv_bfloat16* gA = Ahi + (size_t)(bm + grow) * K + k0 + ghalf;
        const __nv_bfloat16* gAl = Alo + (size_t)(bm + grow) * K + k0 + ghalf;
        const __nv_bfloat16* gB = Bhi + (size_t)(bn + grow) * K + k0 + ghalf;
        const __nv_bfloat16* gBl = Blo + (size_t)(bn + grow) * K + k0 + ghalf;
        CP_ASYNC16(s0 + 0 * MATB,      gA);
        CP_ASYNC16(s0 + 0 * MATB + 16, gA + 8);
        CP_ASYNC16(s0 + 1 * MATB,      gAl);
        CP_ASYNC16(s0 + 1 * MATB + 16, gAl + 8);
        CP_ASYNC16(s0 + 2 * MATB,      gB);
        CP_ASYNC16(s0 + 2 * MATB + 16, gB + 8);
        CP_ASYNC16(s0 + 3 * MATB,      gBl);
        CP_ASYNC16(s0 + 3 * MATB + 16, gBl + 8);
    };

    // ---- ldmatrix lane addressing ----
    // A (16x16 tile): row = (l&15), colByte = (l>>4)*16
    const uint32_t aLane = (uint32_t)(wm + (lid & 15)) * ROWB + ((lid >> 4) << 4);
    // B (n16 x k16): row = (l&7) + ((l>>4)<<3), colByte = ((l>>3)&1)*16
    const uint32_t bLane = (uint32_t)(wn + (lid & 7) + ((lid >> 4) << 3)) * ROWB
                           + (((lid >> 3) & 1) << 4);

    float acc[2][8][4];
    #pragma unroll
    for (int i = 0; i < 2; i++)
        #pragma unroll
        for (int j = 0; j < 8; j++)
            #pragma unroll
            for (int q = 0; q < 4; q++) acc[i][j][q] = 0.0f;

    const int nch = K >> 5;
    issue_stage(0, 0);
    CP_COMMIT();

    for (int c = 0; c < nch; c++) {
        if (c + 1 < nch) {
            issue_stage(c + 1, (c + 1) & 1);
            CP_COMMIT();
            CP_WAIT(1);
        } else {
            CP_WAIT(0);
        }
        __syncthreads();

        const uint32_t stg = sb + (c & 1) * STGB;
        #pragma unroll
        for (int ks = 0; ks < 2; ks++) {
            const uint32_t kb = ks << 5;   // 32B per k16
            uint32_t aF[2][4], bF[4][4];
            // ---- pass hh + hl: A = hi ----
            #pragma unroll
            for (int mt = 0; mt < 2; mt++)
                ldm_x4(aF[mt], stg + 0 * MATB + aLane + mt * (16 * ROWB) + kb);
            #pragma unroll
            for (int g = 0; g < 4; g++)
                ldm_x4(bF[g], stg + 2 * MATB + bLane + g * (16 * ROWB) + kb);
            #pragma unroll
            for (int mt = 0; mt < 2; mt++)
                #pragma unroll
                for (int g = 0; g < 4; g++) {
                    mma_bf16(acc[mt][2 * g],     aF[mt], bF[g][0], bF[g][1]);
                    mma_bf16(acc[mt][2 * g + 1], aF[mt], bF[g][2], bF[g][3]);
                }
            // B = lo
            #pragma unroll
            for (int g = 0; g < 4; g++)
                ldm_x4(bF[g], stg + 3 * MATB + bLane + g * (16 * ROWB) + kb);
            #pragma unroll
            for (int mt = 0; mt < 2; mt++)
                #pragma unroll
                for (int g = 0; g < 4; g++) {
                    mma_bf16(acc[mt][2 * g],     aF[mt], bF[g][0], bF[g][1]);
                    mma_bf16(acc[mt][2 * g + 1], aF[mt], bF[g][2], bF[g][3]);
                }
            // ---- pass lh: A = lo, B = hi ----
            #pragma unroll
            for (int mt = 0; mt < 2; mt++)
                ldm_x4(aF[mt], stg + 1 * MATB + aLane + mt * (16 * ROWB) + kb);
            #pragma unroll
            for (int g = 0; g < 4; g++)
                ldm_x4(bF[g], stg + 2 * MATB + bLane + g * (16 * ROWB) + kb);
            #pragma unroll
            for (int mt = 0; mt < 2; mt++)
                #pragma unroll
                for (int g = 0; g < 4; g++) {
                    mma_bf16(acc[mt][2 * g],     aF[mt], bF[g][0], bF[g][1]);
                    mma_bf16(acc[mt][2 * g + 1], aF[mt], bF[g][2], bF[g][3]);
                }
        }
        __syncthreads();
    }

    // ---- epilogue: c[mt][nt] rows rm+(l>>2)(+8), col cn+nt*8+(l&3)*2 ----
    const int r0 = lid >> 2;
    const int cq = (lid & 3) << 1;
    #pragma unroll
    for (int mt = 0; mt < 2; mt++) {
        #pragma unroll
        for (int half = 0; half < 2; half++) {
            const int row = bm + wm + mt * 16 + r0 + half * 8;
            const size_t base = blockIdx.z * strC + (size_t)row * ldc + bn + wn;
            #pragma unroll
            for (int nt = 0; nt < 8; nt++) {
                const int col = wn + nt * 8 + cq;
                float v0 = acc[mt][nt][half * 2]     * alpha;
                float v1 = acc[mt][nt][half * 2 + 1] * alpha;
                if (bias) {
                    v0 += __ldg(bias + bn + col);
                    v1 += __ldg(bias + bn + col + 1);
                }
                if (Cf)
                    *reinterpret_cast<float2*>(Cf + base + nt * 8 + cq) =
                        make_float2(v0, v1);
                if (Chi) {
                    const __nv_bfloat16 h0 = __float2bfloat16(v0);
                    const __nv_bfloat16 h1 = __float2bfloat16(v1);
                    const float l0 = v0 - __bfloat162float(h0);
                    const float l1 = v1 - __bfloat162float(h1);
                    __nv_bfloat162 hp(h0, h1);
                    __nv_bfloat162 lp(__float2bfloat16(l0), __float2bfloat16(l1));
                    *reinterpret_cast<uint32_t*>(Chi + base + nt * 8 + cq) =
                        *reinterpret_cast<uint32_t*>(&hp);
                    *reinterpret_cast<uint32_t*>(Clo + base + nt * 8 + cq) =
                        *reinterpret_cast<uint32_t*>(&lp);
                }
            }
        }
    }
}

// ---------------------------------------------------------------------------
// fp32 -> bf16 hi/lo split (vectorized)
// ---------------------------------------------------------------------------
__global__ void split_kernel(const float* __restrict__ in,
                             __nv_bfloat16* __restrict__ hi,
                             __nv_bfloat16* __restrict__ lo, int n4)
{
    const int i = blockIdx.x * blockDim.x + threadIdx.x;
    if (i >= n4) return;
    const float4 v = reinterpret_cast<const float4*>(in)[i];
    float f[4] = {v.x, v.y, v.z, v.w};
    float l[4];
    #pragma unroll
    for (int j = 0; j < 4; j++) {
        const __nv_bfloat16 h = __float2bfloat16(f[j]);
        l[j] = f[j] - __bfloat162float(h);
    }
    reinterpret_cast<uint2*>(hi)[i] =
        make_uint2(pack_bf2(f[0], f[1]), pack_bf2(f[2], f[3]));
    reinterpret_cast<uint2*>(lo)[i] =
        make_uint2(pack_bf2(l[0], l[1]), pack_bf2(l[2], l[3]));
}

// ---------------------------------------------------------------------------
// V[B,S,D] fp32 -> Vt[B,D,S] bf16 hi/lo (32x32 SMEM tile transpose)
// ---------------------------------------------------------------------------
__global__ __launch_bounds__(256) void vtrans_split(const float* __restrict__ V,
                                                    __nv_bfloat16* __restrict__ Vth,
                                                    __nv_bfloat16* __restrict__ Vtl)
{
    __shared__ float t[32][33];
    const int b = blockIdx.z;
    const int s0 = blockIdx.x << 5, d0 = blockIdx.y << 5;
    const int tx = threadIdx.x & 31, ty = threadIdx.x >> 5;
    const float* Vb = V + (size_t)b * SS * DD;
    #pragma unroll
    for (int i = 0; i < 4; i++)
        t[ty + i * 8][tx] = Vb[(size_t)(s0 + ty + i * 8) * DD + d0 + tx];
    __syncthreads();
    __nv_bfloat16* th = Vth + (size_t)b * DD * SS;
    __nv_bfloat16* tl = Vtl + (size_t)b * DD * SS;
    #pragma unroll
    for (int i = 0; i < 4; i++) {
        const int d = d0 + ty + i * 8, s = s0 + tx;
        const float f = t[tx][ty + i * 8];
        const __nv_bfloat16 h = __float2bfloat16(f);
        th[(size_t)d * SS + s] = h;
        tl[(size_t)d * SS + s] = __float2bfloat16(f - __bfloat162float(h));
    }
}

// ---------------------------------------------------------------------------
// Row softmax over S=2048, emitting bf16 hi/lo of the result.
// ---------------------------------------------------------------------------
__global__ __launch_bounds__(256) void softmax_split(const float* __restrict__ P,
                                                     __nv_bfloat16* __restrict__ Phi,
                                                     __nv_bfloat16* __restrict__ Plo)
{
    const size_t rowoff = (size_t)blockIdx.x * SS;
    const float* row = P + rowoff;
    const int tid = threadIdx.x;
    __shared__ float red[8];

    float4 v0 = ((const float4*)row)[tid];
    float4 v1 = ((const float4*)row)[tid + 256];

    float m = fmaxf(fmaxf(fmaxf(v0.x, v0.y), fmaxf(v0.z, v0.w)),
                    fmaxf(fmaxf(v1.x, v1.y), fmaxf(v1.z, v1.w)));
    #pragma unroll
    for (int o = 16; o > 0; o >>= 1)
        m = fmaxf(m, __shfl_xor_sync(0xffffffffu, m, o));
    if ((tid & 31) == 0) red[tid >> 5] = m;
    __syncthreads();
    float bmax = red[0];
    #pragma unroll
    for (int i = 1; i < 8; i++) bmax = fmaxf(bmax, red[i]);
    __syncthreads();

    v0.x = __expf(v0.x - bmax); v0.y = __expf(v0.y - bmax);
    v0.z = __expf(v0.z - bmax); v0.w = __expf(v0.w - bmax);
    v1.x = __expf(v1.x - bmax); v1.y = __expf(v1.y - bmax);
    v1.z = __expf(v1.z - bmax); v1.w = __expf(v1.w - bmax);

    float s = v0.x + v0.y + v0.z + v0.w + v1.x + v1.y + v1.z + v1.w;
    #pragma unroll
    for (int o = 16; o > 0; o >>= 1)
        s += __shfl_xor_sync(0xffffffffu, s, o);
    if ((tid & 31) == 0) red[tid >> 5] = s;
    __syncthreads();
    float total = 0.0f;
    #pragma unroll
    for (int i = 0; i < 8; i++) total += red[i];
    const float inv = __frcp_rn(total);

    float f[8] = {v0.x * inv, v0.y * inv, v0.z * inv, v0.w * inv,
                  v1.x * inv, v1.y * inv, v1.z * inv, v1.w * inv};
    float l[8];
    #pragma unroll
    for (int j = 0; j < 8; j++) {
        const __nv_bfloat16 h = __float2bfloat16(f[j]);
        l[j] = f[j] - __bfloat162float(h);
    }
    uint2* ph = reinterpret_cast<uint2*>(Phi + rowoff);
    uint2* pl = reinterpret_cast<uint2*>(Plo + rowoff);
    ph[tid]       = make_uint2(pack_bf2(f[0], f[1]), pack_bf2(f[2], f[3]));
    ph[tid + 256] = make_uint2(pack_bf2(f[4], f[5]), pack_bf2(f[6], f[7]));
    pl[tid]       = make_uint2(pack_bf2(l[0], l[1]), pack_bf2(l[2], l[3]));
    pl[tid + 256] = make_uint2(pack_bf2(l[4], l[5]), pack_bf2(l[6], l[7]));
}

// ---------------------------------------------------------------------------
extern "C" void kernel_launch(void* const* d_in, const int* in_sizes, int n_in,
                              void* d_out, int out_size)
{
    const float* x  = (const float*)d_in[0];
    const float* Wq = (const float*)d_in[1];
    const float* bq = (const float*)d_in[2];
    const float* Wk = (const float*)d_in[3];
    const float* bk = (const float*)d_in[4];
    const float* Wv = (const float*)d_in[5];
    const float* bv = (const float*)d_in[6];
    const float* Wp = (const float*)d_in[7];
    const float* bp = (const float*)d_in[8];
    float* out = (float*)d_out;

    __nv_bfloat16 *xhi, *xlo, *Wqhi, *Wqlo, *Wkhi, *Wklo, *Wvhi, *Wvlo, *Wphi, *Wplo;
    __nv_bfloat16 *Qhi, *Qlo, *Khi, *Klo, *Vthi, *Vtlo, *Phi, *Plo, *Ohi, *Olo;
    float *V, *P;
    cudaGetSymbolAddress((void**)&xhi, g_xhi);   cudaGetSymbolAddress((void**)&xlo, g_xlo);
    cudaGetSymbolAddress((void**)&Wqhi, g_Wqhi); cudaGetSymbolAddress((void**)&Wqlo, g_Wqlo);
    cudaGetSymbolAddress((void**)&Wkhi, g_Wkhi); cudaGetSymbolAddress((void**)&Wklo, g_Wklo);
    cudaGetSymbolAddress((void**)&Wvhi, g_Wvhi); cudaGetSymbolAddress((void**)&Wvlo, g_Wvlo);
    cudaGetSymbolAddress((void**)&Wphi, g_Wphi); cudaGetSymbolAddress((void**)&Wplo, g_Wplo);
    cudaGetSymbolAddress((void**)&Qhi, g_Qhi);   cudaGetSymbolAddress((void**)&Qlo, g_Qlo);
    cudaGetSymbolAddress((void**)&Khi, g_Khi);   cudaGetSymbolAddress((void**)&Klo, g_Klo);
    cudaGetSymbolAddress((void**)&V, g_V);
    cudaGetSymbolAddress((void**)&Vthi, g_Vthi); cudaGetSymbolAddress((void**)&Vtlo, g_Vtlo);
    cudaGetSymbolAddress((void**)&P, g_P);
    cudaGetSymbolAddress((void**)&Phi, g_Phi);   cudaGetSymbolAddress((void**)&Plo, g_Plo);
    cudaGetSymbolAddress((void**)&Ohi, g_Ohi);   cudaGetSymbolAddress((void**)&Olo, g_Olo);

    cudaFuncSetAttribute(mma_gemm, cudaFuncAttributeMaxDynamicSharedMemorySize,
                         GEMM_SMEM_BYTES);

    const float alpha = 1.0f / sqrtf((float)DD);
    const size_t sQK = (size_t)SS * DD;
    const size_t sP  = (size_t)SS * SS;

    // split inputs
    {
        const int n4x = BB * SS * DD / 4;
        split_kernel<<<(n4x + 255) / 256, 256>>>(x, xhi, xlo, n4x);
        const int n4w = DD * DD / 4;
        split_kernel<<<(n4w + 255) / 256, 256>>>(Wq, Wqhi, Wqlo, n4w);
        split_kernel<<<(n4w + 255) / 256, 256>>>(Wk, Wkhi, Wklo, n4w);
        split_kernel<<<(n4w + 255) / 256, 256>>>(Wv, Wvhi, Wvlo, n4w);
        split_kernel<<<(n4w + 255) / 256, 256>>>(Wp, Wphi, Wplo, n4w);
    }

    const dim3 blk(256);
    const dim3 gproj(DD / 128, (BB * SS) / 128, 1);

    // Q = x@Wq^T + bq (emit bf16 hi/lo)
    mma_gemm<<<gproj, blk, GEMM_SMEM_BYTES>>>(xhi, xlo, Wqhi, Wqlo, bq, 1.0f,
                                              nullptr, Qhi, Qlo, DD, DD, 0, 0, 0);
    // K = x@Wk^T + bk
    mma_gemm<<<gproj, blk, GEMM_SMEM_BYTES>>>(xhi, xlo, Wkhi, Wklo, bk, 1.0f,
                                              nullptr, Khi, Klo, DD, DD, 0, 0, 0);
    // V = x@Wv^T + bv (fp32, then transpose-split)
    mma_gemm<<<gproj, blk, GEMM_SMEM_BYTES>>>(xhi, xlo, Wvhi, Wvlo, bv, 1.0f,
                                              V, nullptr, nullptr, DD, DD, 0, 0, 0);
    vtrans_split<<<dim3(SS / 32, DD / 32, BB), blk>>>(V, Vthi, Vtlo);

    // P = (Q@K^T)/sqrt(D) (fp32)
    mma_gemm<<<dim3(SS / 128, SS / 128, BB), blk, GEMM_SMEM_BYTES>>>(
        Qhi, Qlo, Khi, Klo, nullptr, alpha, P, nullptr, nullptr,
        SS, DD, sQK, sQK, sP);

    // softmax rows -> bf16 hi/lo
    softmax_split<<<BB * SS, 256>>>(P, Phi, Plo);

    // O = P@V (NT against Vt[D,S]; emit bf16 hi/lo)
    mma_gemm<<<dim3(DD / 128, SS / 128, BB), blk, GEMM_SMEM_BYTES>>>(
        Phi, Plo, Vthi, Vtlo, nullptr, 1.0f, nullptr, Ohi, Olo,
        DD, SS, sP, (size_t)DD * SS, sQK);

    // out = O@Wp^T + bp (fp32)
    mma_gemm<<<gproj, blk, GEMM_SMEM_BYTES>>>(Ohi, Olo, Wphi, Wplo, bp, 1.0f,
                                              out, nullptr, nullptr, DD, DD, 0, 0, 0);
}

// round 8
// speedup vs baseline: 2.1638x; 1.1813x over previous
#include <cuda_runtime.h>
#include <cuda_bf16.h>
#include <math.h>
#include <stdint.h>

#define BB 8
#define SS 2048
#define DD 768

// ---------------------------------------------------------------------------
// Scratch (device globals: allocation-free per harness rules)
// ---------------------------------------------------------------------------
__device__ __nv_bfloat16 g_xhi[BB * SS * DD], g_xlo[BB * SS * DD];
__device__ __nv_bfloat16 g_Wqhi[DD * DD], g_Wqlo[DD * DD];
__device__ __nv_bfloat16 g_Wkhi[DD * DD], g_Wklo[DD * DD];
__device__ __nv_bfloat16 g_Wvhi[DD * DD], g_Wvlo[DD * DD];
__device__ __nv_bfloat16 g_Wphi[DD * DD], g_Wplo[DD * DD];
__device__ __nv_bfloat16 g_Qhi[BB * SS * DD], g_Qlo[BB * SS * DD];
__device__ __nv_bfloat16 g_Khi[BB * SS * DD], g_Klo[BB * SS * DD];
__device__ float         g_V[BB * SS * DD];
__device__ __nv_bfloat16 g_Vthi[BB * DD * SS], g_Vtlo[BB * DD * SS];
__device__ float         g_P[(size_t)BB * SS * SS];
__device__ __nv_bfloat16 g_Phi[(size_t)BB * SS * SS], g_Plo[(size_t)BB * SS * SS];
__device__ __nv_bfloat16 g_Ohi[BB * SS * DD], g_Olo[BB * SS * DD];

// ---------------------------------------------------------------------------
// Portable PTX helpers (no 'a'-gated features: ldmatrix / mma.sync / cp.async)
// ---------------------------------------------------------------------------
__device__ __forceinline__ uint32_t smem_to_u32(const void* p) {
    uint32_t a;
    asm("{ .reg .u64 t; cvta.to.shared.u64 t, %1; cvt.u32.u64 %0, t; }"
        : "=r"(a) : "l"(p));
    return a;
}

#define CP_ASYNC16(saddr, gaddr) \
    asm volatile("cp.async.cg.shared.global [%0], [%1], 16;" :: "r"(saddr), "l"(gaddr))
#define CP_COMMIT() asm volatile("cp.async.commit_group;" ::: "memory")
#define CP_WAIT(N)  asm volatile("cp.async.wait_group %0;" :: "n"(N) : "memory")

__device__ __forceinline__ void ldm_x4(uint32_t* r, uint32_t addr) {
    asm volatile("ldmatrix.sync.aligned.m8n8.x4.shared.b16 {%0,%1,%2,%3}, [%4];"
                 : "=r"(r[0]), "=r"(r[1]), "=r"(r[2]), "=r"(r[3]) : "r"(addr));
}

__device__ __forceinline__ void mma_bf16(float* c, const uint32_t* a,
                                         uint32_t b0, uint32_t b1) {
    asm volatile(
        "mma.sync.aligned.m16n8k16.row.col.f32.bf16.bf16.f32 "
        "{%0,%1,%2,%3}, {%4,%5,%6,%7}, {%8,%9}, {%0,%1,%2,%3};"
        : "+f"(c[0]), "+f"(c[1]), "+f"(c[2]), "+f"(c[3])
        : "r"(a[0]), "r"(a[1]), "r"(a[2]), "r"(a[3]), "r"(b0), "r"(b1));
}

__device__ __forceinline__ uint32_t pack_bf2(float a, float b) {
    __nv_bfloat162 t(__float2bfloat16(a), __float2bfloat16(b));
    return *reinterpret_cast<uint32_t*>(&t);
}

// ---------------------------------------------------------------------------
// Split-bf16 HMMA GEMM (NT): C[M,N] = alpha*(A @ B^T) + bias
//   A[M,K], B[N,K], both K-contiguous. hi/lo pairs; acc = hh + hl + lh (fp32).
//   128x128 block tile, BK=32, 256 threads, warp tile 32x64, 2 CTAs/SM.
//   grid = (N/128, M/128, batch).
// ---------------------------------------------------------------------------
#define ROWB 80                      // smem row pitch bytes (64B data + 16B pad)
#define MATB (128 * ROWB)            // 10240 B per matrix tile
#define STGB (4 * MATB)              // 40960 B per stage (Ah,Al,Bh,Bl)
#define GEMM_SMEM_BYTES (2 * STGB)   // 81920

__global__ __launch_bounds__(256, 2) void mma_gemm(
    const __nv_bfloat16* __restrict__ Ahi, const __nv_bfloat16* __restrict__ Alo,
    const __nv_bfloat16* __restrict__ Bhi, const __nv_bfloat16* __restrict__ Blo,
    const float* __restrict__ bias, float alpha,
    float* __restrict__ Cf,
    __nv_bfloat16* __restrict__ Chi, __nv_bfloat16* __restrict__ Clo,
    int ldc, int K, size_t strA, size_t strB, size_t strC)
{
    extern __shared__ char smem[];
    const uint32_t sb = smem_to_u32(smem);

    const int tid = threadIdx.x;
    const int wid = tid >> 5;
    const int lid = tid & 31;
    const int bm = blockIdx.y << 7;
    const int bn = blockIdx.x << 7;
    const int wm = (wid & 3) << 5;   // warp row offset (0..96)
    const int wn = (wid >> 2) << 6;  // warp col offset (0,64)

    Ahi += blockIdx.z * strA; Alo += blockIdx.z * strA;
    Bhi += blockIdx.z * strB; Blo += blockIdx.z * strB;

    // ---- global->smem copy geometry (per matrix: 128 rows x 64B) ----
    const int grow = tid >> 1;               // 0..127
    const int ghalf = (tid & 1) << 4;        // element offset 0 / 16
    const uint32_t soff = grow * ROWB + ((tid & 1) << 5);  // byte off in tile

    auto issue_stage = [&](int c, int stg) {
        const int k0 = c << 5;
        const uint32_t s0 = sb + stg * STGB + soff;
        const __nv_bfloat16* gA  = Ahi + (size_t)(bm + grow) * K + k0 + ghalf;
        const __nv_bfloat16* gAl = Alo + (size_t)(bm + grow) * K + k0 + ghalf;
        const __nv_bfloat16* gB  = Bhi + (size_t)(bn + grow) * K + k0 + ghalf;
        const __nv_bfloat16* gBl = Blo + (size_t)(bn + grow) * K + k0 + ghalf;
        CP_ASYNC16(s0 + 0 * MATB,      gA);
        CP_ASYNC16(s0 + 0 * MATB + 16, gA + 8);
        CP_ASYNC16(s0 + 1 * MATB,      gAl);
        CP_ASYNC16(s0 + 1 * MATB + 16, gAl + 8);
        CP_ASYNC16(s0 + 2 * MATB,      gB);
        CP_ASYNC16(s0 + 2 * MATB + 16, gB + 8);
        CP_ASYNC16(s0 + 3 * MATB,      gBl);
        CP_ASYNC16(s0 + 3 * MATB + 16, gBl + 8);
    };

    // ---- ldmatrix lane addressing ----
    // A (16x16 tile): row = (l&15), colByte = (l>>4)*16
    const uint32_t aLane = (uint32_t)(wm + (lid & 15)) * ROWB + ((lid >> 4) << 4);
    // B (n16 x k16): row = (l&7) + ((l>>4)<<3), colByte = ((l>>3)&1)*16
    const uint32_t bLane = (uint32_t)(wn + (lid & 7) + ((lid >> 4) << 3)) * ROWB
                           + (((lid >> 3) & 1) << 4);

    float acc[2][8][4];
    #pragma unroll
    for (int i = 0; i < 2; i++)
        #pragma unroll
        for (int j = 0; j < 8; j++)
            #pragma unroll
            for (int q = 0; q < 4; q++) acc[i][j][q] = 0.0f;

    const int nch = K >> 5;
    issue_stage(0, 0);
    CP_COMMIT();

    for (int c = 0; c < nch; c++) {
        if (c + 1 < nch) {
            issue_stage(c + 1, (c + 1) & 1);
            CP_COMMIT();
            CP_WAIT(1);
        } else {
            CP_WAIT(0);
        }
        __syncthreads();

        const uint32_t stg = sb + (c & 1) * STGB;
        #pragma unroll
        for (int ks = 0; ks < 2; ks++) {
            const uint32_t kb = ks << 5;   // 32B per k16
            uint32_t aH[2][4], aL[2][4], bF[4][4];
            // load A-hi, A-lo, B-hi
            #pragma unroll
            for (int mt = 0; mt < 2; mt++)
                ldm_x4(aH[mt], stg + 0 * MATB + aLane + mt * (16 * ROWB) + kb);
            #pragma unroll
            for (int mt = 0; mt < 2; mt++)
                ldm_x4(aL[mt], stg + 1 * MATB + aLane + mt * (16 * ROWB) + kb);
            #pragma unroll
            for (int g = 0; g < 4; g++)
                ldm_x4(bF[g], stg + 2 * MATB + bLane + g * (16 * ROWB) + kb);
            // hh
            #pragma unroll
            for (int mt = 0; mt < 2; mt++)
                #pragma unroll
                for (int g = 0; g < 4; g++) {
                    mma_bf16(acc[mt][2 * g],     aH[mt], bF[g][0], bF[g][1]);
                    mma_bf16(acc[mt][2 * g + 1], aH[mt], bF[g][2], bF[g][3]);
                }
            // lh (B-hi still resident)
            #pragma unroll
            for (int mt = 0; mt < 2; mt++)
                #pragma unroll
                for (int g = 0; g < 4; g++) {
                    mma_bf16(acc[mt][2 * g],     aL[mt], bF[g][0], bF[g][1]);
                    mma_bf16(acc[mt][2 * g + 1], aL[mt], bF[g][2], bF[g][3]);
                }
            // load B-lo into the same fragment regs, then hl
            #pragma unroll
            for (int g = 0; g < 4; g++)
                ldm_x4(bF[g], stg + 3 * MATB + bLane + g * (16 * ROWB) + kb);
            #pragma unroll
            for (int mt = 0; mt < 2; mt++)
                #pragma unroll
                for (int g = 0; g < 4; g++) {
                    mma_bf16(acc[mt][2 * g],     aH[mt], bF[g][0], bF[g][1]);
                    mma_bf16(acc[mt][2 * g + 1], aH[mt], bF[g][2], bF[g][3]);
                }
        }
        __syncthreads();
    }

    // ---- epilogue: c[mt][nt] rows rm+(l>>2)(+8), col cn+nt*8+(l&3)*2 ----
    const int r0 = lid >> 2;
    const int cq = (lid & 3) << 1;
    #pragma unroll
    for (int mt = 0; mt < 2; mt++) {
        #pragma unroll
        for (int half = 0; half < 2; half++) {
            const int row = bm + wm + mt * 16 + r0 + half * 8;
            const size_t base = blockIdx.z * strC + (size_t)row * ldc + bn + wn;
            #pragma unroll
            for (int nt = 0; nt < 8; nt++) {
                const int col = wn + nt * 8 + cq;
                float v0 = acc[mt][nt][half * 2]     * alpha;
                float v1 = acc[mt][nt][half * 2 + 1] * alpha;
                if (bias) {
                    v0 += __ldg(bias + bn + col);
                    v1 += __ldg(bias + bn + col + 1);
                }
                if (Cf)
                    __stcs(reinterpret_cast<float2*>(Cf + base + nt * 8 + cq),
                           make_float2(v0, v1));
                if (Chi) {
                    const __nv_bfloat16 h0 = __float2bfloat16(v0);
                    const __nv_bfloat16 h1 = __float2bfloat16(v1);
                    const float l0 = v0 - __bfloat162float(h0);
                    const float l1 = v1 - __bfloat162float(h1);
                    __nv_bfloat162 hp(h0, h1);
                    __nv_bfloat162 lp(__float2bfloat16(l0), __float2bfloat16(l1));
                    *reinterpret_cast<uint32_t*>(Chi + base + nt * 8 + cq) =
                        *reinterpret_cast<uint32_t*>(&hp);
                    *reinterpret_cast<uint32_t*>(Clo + base + nt * 8 + cq) =
                        *reinterpret_cast<uint32_t*>(&lp);
                }
            }
        }
    }
}

// ---------------------------------------------------------------------------
// fp32 -> bf16 hi/lo split (vectorized)
// ---------------------------------------------------------------------------
__global__ void split_kernel(const float* __restrict__ in,
                             __nv_bfloat16* __restrict__ hi,
                             __nv_bfloat16* __restrict__ lo, int n4)
{
    const int i = blockIdx.x * blockDim.x + threadIdx.x;
    if (i >= n4) return;
    const float4 v = reinterpret_cast<const float4*>(in)[i];
    float f[4] = {v.x, v.y, v.z, v.w};
    float l[4];
    #pragma unroll
    for (int j = 0; j < 4; j++) {
        const __nv_bfloat16 h = __float2bfloat16(f[j]);
        l[j] = f[j] - __bfloat162float(h);
    }
    reinterpret_cast<uint2*>(hi)[i] =
        make_uint2(pack_bf2(f[0], f[1]), pack_bf2(f[2], f[3]));
    reinterpret_cast<uint2*>(lo)[i] =
        make_uint2(pack_bf2(l[0], l[1]), pack_bf2(l[2], l[3]));
}

// ---------------------------------------------------------------------------
// V[B,S,D] fp32 -> Vt[B,D,S] bf16 hi/lo (32x32 SMEM tile transpose)
// ---------------------------------------------------------------------------
__global__ __launch_bounds__(256) void vtrans_split(const float* __restrict__ V,
                                                    __nv_bfloat16* __restrict__ Vth,
                                                    __nv_bfloat16* __restrict__ Vtl)
{
    __shared__ float t[32][33];
    const int b = blockIdx.z;
    const int s0 = blockIdx.x << 5, d0 = blockIdx.y << 5;
    const int tx = threadIdx.x & 31, ty = threadIdx.x >> 5;
    const float* Vb = V + (size_t)b * SS * DD;
    #pragma unroll
    for (int i = 0; i < 4; i++)
        t[ty + i * 8][tx] = Vb[(size_t)(s0 + ty + i * 8) * DD + d0 + tx];
    __syncthreads();
    __nv_bfloat16* th = Vth + (size_t)b * DD * SS;
    __nv_bfloat16* tl = Vtl + (size_t)b * DD * SS;
    #pragma unroll
    for (int i = 0; i < 4; i++) {
        const int d = d0 + ty + i * 8, s = s0 + tx;
        const float f = t[tx][ty + i * 8];
        const __nv_bfloat16 h = __float2bfloat16(f);
        th[(size_t)d * SS + s] = h;
        tl[(size_t)d * SS + s] = __float2bfloat16(f - __bfloat162float(h));
    }
}

// ---------------------------------------------------------------------------
// Row softmax over S=2048, emitting bf16 hi/lo of the result.
// ---------------------------------------------------------------------------
__global__ __launch_bounds__(256) void softmax_split(const float* __restrict__ P,
                                                     __nv_bfloat16* __restrict__ Phi,
                                                     __nv_bfloat16* __restrict__ Plo)
{
    const size_t rowoff = (size_t)blockIdx.x * SS;
    const float* row = P + rowoff;
    const int tid = threadIdx.x;
    __shared__ float red[8];

    float4 v0 = __ldcs(((const float4*)row) + tid);
    float4 v1 = __ldcs(((const float4*)row) + tid + 256);

    float m = fmaxf(fmaxf(fmaxf(v0.x, v0.y), fmaxf(v0.z, v0.w)),
                    fmaxf(fmaxf(v1.x, v1.y), fmaxf(v1.z, v1.w)));
    #pragma unroll
    for (int o = 16; o > 0; o >>= 1)
        m = fmaxf(m, __shfl_xor_sync(0xffffffffu, m, o));
    if ((tid & 31) == 0) red[tid >> 5] = m;
    __syncthreads();
    float bmax = red[0];
    #pragma unroll
    for (int i = 1; i < 8; i++) bmax = fmaxf(bmax, red[i]);
    __syncthreads();

    v0.x = __expf(v0.x - bmax); v0.y = __expf(v0.y - bmax);
    v0.z = __expf(v0.z - bmax); v0.w = __expf(v0.w - bmax);
    v1.x = __expf(v1.x - bmax); v1.y = __expf(v1.y - bmax);
    v1.z = __expf(v1.z - bmax); v1.w = __expf(v1.w - bmax);

    float s = v0.x + v0.y + v0.z + v0.w + v1.x + v1.y + v1.z + v1.w;
    #pragma unroll
    for (int o = 16; o > 0; o >>= 1)
        s += __shfl_xor_sync(0xffffffffu, s, o);
    if ((tid & 31) == 0) red[tid >> 5] = s;
    __syncthreads();
    float total = 0.0f;
    #pragma unroll
    for (int i = 0; i < 8; i++) total += red[i];
    const float inv = __frcp_rn(total);

    float f[8] = {v0.x * inv, v0.y * inv, v0.z * inv, v0.w * inv,
                  v1.x * inv, v1.y * inv, v1.z * inv, v1.w * inv};
    float l[8];
    #pragma unroll
    for (int j = 0; j < 8; j++) {
        const __nv_bfloat16 h = __float2bfloat16(f[j]);
        l[j] = f[j] - __bfloat162float(h);
    }
    uint2* ph = reinterpret_cast<uint2*>(Phi + rowoff);
    uint2* pl = reinterpret_cast<uint2*>(Plo + rowoff);
    ph[tid]       = make_uint2(pack_bf2(f[0], f[1]), pack_bf2(f[2], f[3]));
    ph[tid + 256] = make_uint2(pack_bf2(f[4], f[5]), pack_bf2(f[6], f[7]));
    pl[tid]       = make_uint2(pack_bf2(l[0], l[1]), pack_bf2(l[2], l[3]));
    pl[tid + 256] = make_uint2(pack_bf2(l[4], l[5]), pack_bf2(l[6], l[7]));
}

// ---------------------------------------------------------------------------
extern "C" void kernel_launch(void* const* d_in, const int* in_sizes, int n_in,
                              void* d_out, int out_size)
{
    const float* x  = (const float*)d_in[0];
    const float* Wq = (const float*)d_in[1];
    const float* bq = (const float*)d_in[2];
    const float* Wk = (const float*)d_in[3];
    const float* bk = (const float*)d_in[4];
    const float* Wv = (const float*)d_in[5];
    const float* bv = (const float*)d_in[6];
    const float* Wp = (const float*)d_in[7];
    const float* bp = (const float*)d_in[8];
    float* out = (float*)d_out;

    __nv_bfloat16 *xhi, *xlo, *Wqhi, *Wqlo, *Wkhi, *Wklo, *Wvhi, *Wvlo, *Wphi, *Wplo;
    __nv_bfloat16 *Qhi, *Qlo, *Khi, *Klo, *Vthi, *Vtlo, *Phi, *Plo, *Ohi, *Olo;
    float *V, *P;
    cudaGetSymbolAddress((void**)&xhi, g_xhi);   cudaGetSymbolAddress((void**)&xlo, g_xlo);
    cudaGetSymbolAddress((void**)&Wqhi, g_Wqhi); cudaGetSymbolAddress((void**)&Wqlo, g_Wqlo);
    cudaGetSymbolAddress((void**)&Wkhi, g_Wkhi); cudaGetSymbolAddress((void**)&Wklo, g_Wklo);
    cudaGetSymbolAddress((void**)&Wvhi, g_Wvhi); cudaGetSymbolAddress((void**)&Wvlo, g_Wvlo);
    cudaGetSymbolAddress((void**)&Wphi, g_Wphi); cudaGetSymbolAddress((void**)&Wplo, g_Wplo);
    cudaGetSymbolAddress((void**)&Qhi, g_Qhi);   cudaGetSymbolAddress((void**)&Qlo, g_Qlo);
    cudaGetSymbolAddress((void**)&Khi, g_Khi);   cudaGetSymbolAddress((void**)&Klo, g_Klo);
    cudaGetSymbolAddress((void**)&V, g_V);
    cudaGetSymbolAddress((void**)&Vthi, g_Vthi); cudaGetSymbolAddress((void**)&Vtlo, g_Vtlo);
    cudaGetSymbolAddress((void**)&P, g_P);
    cudaGetSymbolAddress((void**)&Phi, g_Phi);   cudaGetSymbolAddress((void**)&Plo, g_Plo);
    cudaGetSymbolAddress((void**)&Ohi, g_Ohi);   cudaGetSymbolAddress((void**)&Olo, g_Olo);

    cudaFuncSetAttribute(mma_gemm, cudaFuncAttributeMaxDynamicSharedMemorySize,
                         GEMM_SMEM_BYTES);

    const float alpha = 1.0f / sqrtf((float)DD);
    const size_t sQK = (size_t)SS * DD;
    const size_t sP  = (size_t)SS * SS;

    // split inputs
    {
        const int n4x = BB * SS * DD / 4;
        split_kernel<<<(n4x + 255) / 256, 256>>>(x, xhi, xlo, n4x);
        const int n4w = DD * DD / 4;
        split_kernel<<<(n4w + 255) / 256, 256>>>(Wq, Wqhi, Wqlo, n4w);
        split_kernel<<<(n4w + 255) / 256, 256>>>(Wk, Wkhi, Wklo, n4w);
        split_kernel<<<(n4w + 255) / 256, 256>>>(Wv, Wvhi, Wvlo, n4w);
        split_kernel<<<(n4w + 255) / 256, 256>>>(Wp, Wphi, Wplo, n4w);
    }

    const dim3 blk(256);
    const dim3 gproj(DD / 128, (BB * SS) / 128, 1);

    // Q = x@Wq^T + bq (emit bf16 hi/lo)
    mma_gemm<<<gproj, blk, GEMM_SMEM_BYTES>>>(xhi, xlo, Wqhi, Wqlo, bq, 1.0f,
                                              nullptr, Qhi, Qlo, DD, DD, 0, 0, 0);
    // K = x@Wk^T + bk
    mma_gemm<<<gproj, blk, GEMM_SMEM_BYTES>>>(xhi, xlo, Wkhi, Wklo, bk, 1.0f,
                                              nullptr, Khi, Klo, DD, DD, 0, 0, 0);
    // V = x@Wv^T + bv (fp32, then transpose-split)
    mma_gemm<<<gproj, blk, GEMM_SMEM_BYTES>>>(xhi, xlo, Wvhi, Wvlo, bv, 1.0f,
                                              V, nullptr, nullptr, DD, DD, 0, 0, 0);
    vtrans_split<<<dim3(SS / 32, DD / 32, BB), blk>>>(V, Vthi, Vtlo);

    // P = (Q@K^T)/sqrt(D) (fp32)
    mma_gemm<<<dim3(SS / 128, SS / 128, BB), blk, GEMM_SMEM_BYTES>>>(
        Qhi, Qlo, Khi, Klo, nullptr, alpha, P, nullptr, nullptr,
        SS, DD, sQK, sQK, sP);

    // softmax rows -> bf16 hi/lo
    softmax_split<<<BB * SS, 256>>>(P, Phi, Plo);

    // O = P@V (NT against Vt[D,S]; emit bf16 hi/lo)
    mma_gemm<<<dim3(DD / 128, SS / 128, BB), blk, GEMM_SMEM_BYTES>>>(
        Phi, Plo, Vthi, Vtlo, nullptr, 1.0f, nullptr, Ohi, Olo,
        DD, SS, sP, (size_t)DD * SS, sQK);

    // out = O@Wp^T + bp (fp32)
    mma_gemm<<<gproj, blk, GEMM_SMEM_BYTES>>>(Ohi, Olo, Wphi, Wplo, bp, 1.0f,
                                              out, nullptr, nullptr, DD, DD, 0, 0, 0);
}